// round 5
// baseline (speedup 1.0000x reference)
#include <cuda_runtime.h>
#include <cuda_bf16.h>
#include <math.h>
#include <stdint.h>

#define BATCH   2
#define SEQ     2048
#define DMODEL  1024
#define NHEADS  16
#define HDIM    64
#define WIN     64
#define MTOT    (BATCH*SEQ)   // 4096
#define WSZ     (DMODEL*DMODEL)

// ---------------- scratch (static device globals) ----------------
__device__ __nv_bfloat16 g_xh[MTOT*DMODEL];
__device__ __nv_bfloat16 g_xl[MTOT*DMODEL];
__device__ __nv_bfloat16 g_wh[4*WSZ];   // original [k][n] layout, bf16 hi
__device__ __nv_bfloat16 g_wl[4*WSZ];   // original [k][n] layout, bf16 lo
__device__ __nv_bfloat16 g_qh[MTOT*DMODEL];
__device__ __nv_bfloat16 g_ql[MTOT*DMODEL];
__device__ __nv_bfloat16 g_kh[MTOT*DMODEL];
__device__ __nv_bfloat16 g_kl[MTOT*DMODEL];
__device__ __nv_bfloat16 g_vh[MTOT*DMODEL];
__device__ __nv_bfloat16 g_vl[MTOT*DMODEL];
__device__ __nv_bfloat16 g_ah[MTOT*DMODEL];  // attention out, bf16 hi
__device__ __nv_bfloat16 g_al[MTOT*DMODEL];  // attention out, bf16 lo

// ---------------- PTX helpers (non-'a' features only) ----------------
__device__ __forceinline__ uint32_t smem_u32(const void* p) {
    uint32_t a;
    asm("{ .reg .u64 t; cvta.to.shared.u64 t, %1; cvt.u32.u64 %0, t; }" : "=r"(a) : "l"(p));
    return a;
}
__device__ __forceinline__ void cp_async16(uint32_t s, const void* g) {
    asm volatile("cp.async.cg.shared.global [%0], [%1], 16;" :: "r"(s), "l"(g));
}
__device__ __forceinline__ void cp_async16z(uint32_t s, const void* g, uint32_t srcsz) {
    asm volatile("cp.async.cg.shared.global [%0], [%1], 16, %2;" :: "r"(s), "l"(g), "r"(srcsz));
}
#define CP_COMMIT() asm volatile("cp.async.commit_group;" ::: "memory")
#define CP_WAIT(n)  asm volatile("cp.async.wait_group %0;" :: "n"(n) : "memory")

__device__ __forceinline__ void ldsm_x4(uint32_t* r, uint32_t a) {
    asm volatile("ldmatrix.sync.aligned.m8n8.x4.shared.b16 {%0,%1,%2,%3}, [%4];"
        : "=r"(r[0]), "=r"(r[1]), "=r"(r[2]), "=r"(r[3]) : "r"(a));
}
__device__ __forceinline__ void ldsm_x2(uint32_t* r, uint32_t a) {
    asm volatile("ldmatrix.sync.aligned.m8n8.x2.shared.b16 {%0,%1}, [%2];"
        : "=r"(r[0]), "=r"(r[1]) : "r"(a));
}
__device__ __forceinline__ void ldsm_x2t(uint32_t* r, uint32_t a) {
    asm volatile("ldmatrix.sync.aligned.m8n8.x2.trans.shared.b16 {%0,%1}, [%2];"
        : "=r"(r[0]), "=r"(r[1]) : "r"(a));
}
__device__ __forceinline__ void mma_bf16(float* d, const uint32_t* a, const uint32_t* b) {
    asm volatile(
        "mma.sync.aligned.m16n8k16.row.col.f32.bf16.bf16.f32 "
        "{%0,%1,%2,%3}, {%4,%5,%6,%7}, {%8,%9}, {%0,%1,%2,%3};"
        : "+f"(d[0]), "+f"(d[1]), "+f"(d[2]), "+f"(d[3])
        : "r"(a[0]), "r"(a[1]), "r"(a[2]), "r"(a[3]), "r"(b[0]), "r"(b[1]));
}

__device__ __forceinline__ uint32_t pack_bf2(float x, float y) {
    __nv_bfloat162 h;
    h.x = __float2bfloat16(x); h.y = __float2bfloat16(y);
    return *(uint32_t*)&h;
}

// ============================================================
// Conversion kernels (pure streaming, no transpose)
// ============================================================
__global__ __launch_bounds__(256) void convert_x_kernel(const float* __restrict__ x)
{
    size_t off = (size_t)blockIdx.x * DMODEL + threadIdx.x * 4;
    float4 v = *(const float4*)(x + off);
    __nv_bfloat162 h01, h23, l01, l23;
    h01.x = __float2bfloat16(v.x); l01.x = __float2bfloat16(v.x - __bfloat162float(h01.x));
    h01.y = __float2bfloat16(v.y); l01.y = __float2bfloat16(v.y - __bfloat162float(h01.y));
    h23.x = __float2bfloat16(v.z); l23.x = __float2bfloat16(v.z - __bfloat162float(h23.x));
    h23.y = __float2bfloat16(v.w); l23.y = __float2bfloat16(v.w - __bfloat162float(h23.y));
    *(__nv_bfloat162*)(g_xh + off) = h01; *(__nv_bfloat162*)(g_xh + off + 2) = h23;
    *(__nv_bfloat162*)(g_xl + off) = l01; *(__nv_bfloat162*)(g_xl + off + 2) = l23;
}

__global__ __launch_bounds__(256) void convert_w_kernel(
    const float* __restrict__ Wq, const float* __restrict__ Wk,
    const float* __restrict__ Wv, const float* __restrict__ Wo)
{
    int z = blockIdx.y;
    const float* W = (z == 0) ? Wq : (z == 1) ? Wk : (z == 2) ? Wv : Wo;
    size_t off = (size_t)blockIdx.x * DMODEL + threadIdx.x * 4;
    float4 v = *(const float4*)(W + off);
    __nv_bfloat162 h01, h23, l01, l23;
    h01.x = __float2bfloat16(v.x); l01.x = __float2bfloat16(v.x - __bfloat162float(h01.x));
    h01.y = __float2bfloat16(v.y); l01.y = __float2bfloat16(v.y - __bfloat162float(h01.y));
    h23.x = __float2bfloat16(v.z); l23.x = __float2bfloat16(v.z - __bfloat162float(h23.x));
    h23.y = __float2bfloat16(v.w); l23.y = __float2bfloat16(v.w - __bfloat162float(h23.y));
    size_t o = (size_t)z * WSZ + off;
    *(__nv_bfloat162*)(g_wh + o) = h01; *(__nv_bfloat162*)(g_wh + o + 2) = h23;
    *(__nv_bfloat162*)(g_wl + o) = l01; *(__nv_bfloat162*)(g_wl + o + 2) = l23;
}

// ============================================================
// Split-bf16 HMMA GEMM: C = A @ W + bias, W in [k][n] layout.
// CTA tile 128x128, BK=32, 8 warps, 4-stage cp.async pipeline.
// A smem: [128 m][32 k], pitch 80B.  B smem: [32 k][128 n], pitch 272B.
// B fragments via ldmatrix.trans.
// ============================================================
#define BK        32
#define APITCHB_G 80
#define MAT_A     (128*APITCHB_G)      // 10240 B
#define BPITCHB_G 272
#define MAT_BG    (32*BPITCHB_G)       // 8704 B
#define OFF_AH    0
#define OFF_AL    MAT_A
#define OFF_BH    (2*MAT_A)
#define OFF_BL    (2*MAT_A + MAT_BG)
#define STAGE_SZ  (2*MAT_A + 2*MAT_BG) // 37888 B
#define NSTAGE    4
#define GEMM_SMEM (NSTAGE*STAGE_SZ)    // 151552 B

__global__ __launch_bounds__(256) void hmma_gemm_kernel(
    int mode, const float* __restrict__ b0, const float* __restrict__ b1,
    const float* __restrict__ b2, float* __restrict__ outp)
{
    extern __shared__ char sm[];
    const uint32_t sbase = smem_u32(sm);

    const int tid  = threadIdx.x;
    const int lane = tid & 31;
    const int wid  = tid >> 5;
    const int wm   = wid >> 2;
    const int wn   = wid & 3;
    const int m0   = blockIdx.y * 128;
    const int n0   = blockIdx.x * 128;
    const int z    = blockIdx.z;

    const __nv_bfloat16 *Ah, *Al, *Bh, *Bl;
    const float* bias;
    if (mode == 0) {
        Ah = g_xh; Al = g_xl;
        Bh = g_wh + (size_t)z * WSZ; Bl = g_wl + (size_t)z * WSZ;
        bias = (z == 0) ? b0 : (z == 1) ? b1 : b2;
    } else {
        Ah = g_ah; Al = g_al;
        Bh = g_wh + 3ull * WSZ; Bl = g_wl + 3ull * WSZ;
        bias = b0;
    }

    // A: 512 tasks (128 rows x 4 segs of 16B); B: 512 tasks (32 rows x 16 segs)
    const int arw0 = tid >> 1;                 // not used directly; per-task calc below
    (void)arw0;

#define PREFETCH(stage, cc) do {                                               \
    const int _k0 = (cc) * BK;                                                 \
    const uint32_t _sb = sbase + (uint32_t)(stage) * STAGE_SZ;                 \
    _Pragma("unroll")                                                          \
    for (int _i = 0; _i < 2; _i++) {                                           \
        int _t = tid + _i * 256;                                               \
        int _r = _t >> 2, _sg = _t & 3;                                        \
        uint32_t _sa = _sb + (uint32_t)_r * APITCHB_G + (uint32_t)_sg * 16;    \
        size_t _ga = (size_t)(m0 + _r) * DMODEL + _k0 + _sg * 8;               \
        cp_async16(_sa + OFF_AH, Ah + _ga);                                    \
        cp_async16(_sa + OFF_AL, Al + _ga);                                    \
        int _rb = _t >> 4, _sgb = _t & 15;                                     \
        uint32_t _sbb = _sb + (uint32_t)_rb * BPITCHB_G + (uint32_t)_sgb * 16; \
        size_t _gb = (size_t)(_k0 + _rb) * DMODEL + n0 + _sgb * 8;             \
        cp_async16(_sbb + OFF_BH, Bh + _gb);                                   \
        cp_async16(_sbb + OFF_BL, Bl + _gb);                                   \
    }                                                                          \
} while (0)

    float acc[4][4][4];
#pragma unroll
    for (int i = 0; i < 4; i++)
#pragma unroll
        for (int j = 0; j < 4; j++)
#pragma unroll
            for (int e = 0; e < 4; e++) acc[i][j][e] = 0.f;

    const int arow_l = ((lane >> 3) & 1) * 8 + (lane & 7);
    const int akoff  = (lane >> 4) * 8;
    const int btrow  = ((lane >> 3) & 1) * 8 + (lane & 7);   // trans-B row within k16

    PREFETCH(0, 0); CP_COMMIT();
    PREFETCH(1, 1); CP_COMMIT();
    PREFETCH(2, 2); CP_COMMIT();

    const int NCHUNK = DMODEL / BK;   // 32
    for (int c = 0; c < NCHUNK; c++) {
        if (c < NCHUNK - 2)      { CP_WAIT(2); }
        else if (c == NCHUNK - 2){ CP_WAIT(1); }
        else                     { CP_WAIT(0); }
        __syncthreads();
        if (c + 3 < NCHUNK) { PREFETCH((c + 3) & 3, c + 3); CP_COMMIT(); }

        const uint32_t stb = sbase + (uint32_t)(c & 3) * STAGE_SZ;
#pragma unroll
        for (int ks = 0; ks < 2; ks++) {
            uint32_t ah[4][4], al[4][4], bh[4][2], bl[4][2];
#pragma unroll
            for (int mt = 0; mt < 4; mt++) {
                uint32_t ad = stb + OFF_AH + (uint32_t)(wm * 64 + mt * 16 + arow_l) * APITCHB_G
                                  + (uint32_t)(ks * 16 + akoff) * 2;
                ldsm_x4(ah[mt], ad);
                ldsm_x4(al[mt], ad + (OFF_AL - OFF_AH));
            }
#pragma unroll
            for (int nt = 0; nt < 4; nt++) {
                uint32_t bd = stb + OFF_BH + (uint32_t)(ks * 16 + btrow) * BPITCHB_G
                                  + (uint32_t)(wn * 32 + nt * 8) * 2;
                ldsm_x2t(bh[nt], bd);
                ldsm_x2t(bl[nt], bd + (OFF_BL - OFF_BH));
            }
#pragma unroll
            for (int mt = 0; mt < 4; mt++)
#pragma unroll
                for (int nt = 0; nt < 4; nt++) {
                    mma_bf16(acc[mt][nt], ah[mt], bh[nt]);
                    mma_bf16(acc[mt][nt], ah[mt], bl[nt]);
                    mma_bf16(acc[mt][nt], al[mt], bh[nt]);
                }
        }
        __syncthreads();
    }

    const int g     = lane >> 2;
    const int cpair = (lane & 3) * 2;
    if (mode == 0) {
        __nv_bfloat16* Ch = (z == 0) ? g_qh : (z == 1) ? g_kh : g_vh;
        __nv_bfloat16* Cl = (z == 0) ? g_ql : (z == 1) ? g_kl : g_vl;
#pragma unroll
        for (int mt = 0; mt < 4; mt++) {
            int row0 = m0 + wm * 64 + mt * 16 + g;
#pragma unroll
            for (int nt = 0; nt < 4; nt++) {
                int col = n0 + wn * 32 + nt * 8 + cpair;
                float bx = bias[col], by = bias[col + 1];
#pragma unroll
                for (int rr = 0; rr < 2; rr++) {
                    float o0 = acc[mt][nt][rr * 2 + 0] + bx;
                    float o1 = acc[mt][nt][rr * 2 + 1] + by;
                    __nv_bfloat162 h2, l2;
                    h2.x = __float2bfloat16(o0); l2.x = __float2bfloat16(o0 - __bfloat162float(h2.x));
                    h2.y = __float2bfloat16(o1); l2.y = __float2bfloat16(o1 - __bfloat162float(h2.y));
                    size_t off = (size_t)(row0 + rr * 8) * DMODEL + col;
                    *(__nv_bfloat162*)(Ch + off) = h2;
                    *(__nv_bfloat162*)(Cl + off) = l2;
                }
            }
        }
    } else {
        float* C = outp;
#pragma unroll
        for (int mt = 0; mt < 4; mt++) {
            int row0 = m0 + wm * 64 + mt * 16 + g;
#pragma unroll
            for (int nt = 0; nt < 4; nt++) {
                int col = n0 + wn * 32 + nt * 8 + cpair;
                float bx = bias[col], by = bias[col + 1];
                *(float2*)(C + (size_t)row0 * DMODEL + col) =
                    make_float2(acc[mt][nt][0] + bx, acc[mt][nt][1] + by);
                *(float2*)(C + (size_t)(row0 + 8) * DMODEL + col) =
                    make_float2(acc[mt][nt][2] + bx, acc[mt][nt][3] + by);
            }
        }
    }
#undef PREFETCH
}

// ============================================================
// Banded flash-attention with mma.sync (split bf16 hi/lo)
// CTA = (64 queries, head, batch); 4 warps; warp = 16 query rows.
// ============================================================
#define APITCH   72
#define APITCHB  144
#define A_QH     0
#define A_QL     9216
#define A_KH     18432
#define A_KL     46080
#define A_VH     73728
#define A_VL     101376
#define ATTN_SMEM 129024

__global__ __launch_bounds__(128) void attn_mma_kernel()
{
    extern __shared__ char sm[];
    const uint32_t sb = smem_u32(sm);

    const int tid  = threadIdx.x;
    const int lane = tid & 31;
    const int w    = tid >> 5;
    const int b    = blockIdx.z;
    const int h    = blockIdx.y;
    const int q0   = blockIdx.x * 64;
    const int kbase = q0 - WIN;
    const size_t tok0 = (size_t)b * SEQ;
    const int coff = h * HDIM;

#pragma unroll
    for (int i = 0; i < 4; i++) {
        int task = tid + i * 128;
        int row = task >> 3, seg = task & 7;
        uint32_t d = sb + A_QH + (uint32_t)row * APITCHB + (uint32_t)seg * 16;
        size_t goff = (tok0 + q0 + row) * DMODEL + coff + seg * 8;
        cp_async16(d,                 g_qh + goff);
        cp_async16(d + (A_QL - A_QH), g_ql + goff);
    }
#pragma unroll
    for (int i = 0; i < 12; i++) {
        int task = tid + i * 128;
        int row = task >> 3, seg = task & 7;
        int kg = kbase + row;
        int kgc = min(max(kg, 0), SEQ - 1);
        uint32_t sz = (kg >= 0 && kg < SEQ) ? 16u : 0u;
        uint32_t d = sb + A_KH + (uint32_t)row * APITCHB + (uint32_t)seg * 16;
        size_t goff = (tok0 + kgc) * DMODEL + coff + seg * 8;
        cp_async16z(d,                 g_kh + goff, sz);
        cp_async16z(d + (A_KL - A_KH), g_kl + goff, sz);
    }
    CP_COMMIT();
#pragma unroll
    for (int i = 0; i < 12; i++) {
        int task = tid + i * 128;
        int row = task >> 3, seg = task & 7;
        int kg = kbase + row;
        int kgc = min(max(kg, 0), SEQ - 1);
        uint32_t sz = (kg >= 0 && kg < SEQ) ? 16u : 0u;
        uint32_t d = sb + A_VH + (uint32_t)row * APITCHB + (uint32_t)seg * 16;
        size_t goff = (tok0 + kgc) * DMODEL + coff + seg * 8;
        cp_async16z(d,                 g_vh + goff, sz);
        cp_async16z(d + (A_VL - A_VH), g_vl + goff, sz);
    }
    CP_COMMIT();

    CP_WAIT(1);
    __syncthreads();

    const int arow = w * 16 + ((lane >> 3) & 1) * 8 + (lane & 7);
    const int akoff = (lane >> 4) * 8;
    uint32_t qfh[4][4], qfl[4][4];
#pragma unroll
    for (int kc = 0; kc < 4; kc++) {
        uint32_t ad = sb + A_QH + (uint32_t)arow * APITCHB + (uint32_t)(kc * 16 + akoff) * 2;
        ldsm_x4(qfh[kc], ad);
        ldsm_x4(qfl[kc], ad + (A_QL - A_QH));
    }

    float s[18][4];
#pragma unroll
    for (int t = 0; t < 18; t++)
#pragma unroll
        for (int e = 0; e < 4; e++) s[t][e] = 0.f;

    const int brow = lane & 7;
    const int bko  = ((lane >> 3) & 1) * 8;
#pragma unroll
    for (int t = 0; t < 18; t++) {
        int nt = 2 * w + t;
        uint32_t kb_addr = sb + A_KH + (uint32_t)(nt * 8 + brow) * APITCHB + (uint32_t)bko * 2;
#pragma unroll
        for (int kc = 0; kc < 4; kc++) {
            uint32_t kfh[2], kfl[2];
            uint32_t ka = kb_addr + (uint32_t)kc * 32;
            ldsm_x2(kfh, ka);
            ldsm_x2(kfl, ka + (A_KL - A_KH));
            mma_bf16(s[t], qfh[kc], kfh);
            mma_bf16(s[t], qfh[kc], kfl);
            mma_bf16(s[t], qfl[kc], kfh);
        }
    }

    const int g  = lane >> 2;
    const int c2 = (lane & 3) * 2;
    const int qg0 = q0 + w * 16 + g;
    const int qg1 = qg0 + 8;
    const float scale = 0.125f;

    float m0 = -1e30f, m1 = -1e30f;
#pragma unroll
    for (int t = 0; t < 18; t++) {
        int j0 = (2 * w + t) * 8 + c2;
        int kg0 = kbase + j0, kg1 = kg0 + 1;
        bool in0 = (kg0 >= 0) && (kg0 < SEQ);
        bool in1 = (kg1 >= 0) && (kg1 < SEQ);
        int d00 = kg0 - qg0, d10 = kg1 - qg0, d01 = kg0 - qg1, d11 = kg1 - qg1;
        s[t][0] = (in0 && d00 <= WIN && d00 >= -WIN) ? s[t][0] * scale : -1e30f;
        s[t][1] = (in1 && d10 <= WIN && d10 >= -WIN) ? s[t][1] * scale : -1e30f;
        s[t][2] = (in0 && d01 <= WIN && d01 >= -WIN) ? s[t][2] * scale : -1e30f;
        s[t][3] = (in1 && d11 <= WIN && d11 >= -WIN) ? s[t][3] * scale : -1e30f;
        m0 = fmaxf(m0, fmaxf(s[t][0], s[t][1]));
        m1 = fmaxf(m1, fmaxf(s[t][2], s[t][3]));
    }
    m0 = fmaxf(m0, __shfl_xor_sync(0xffffffffu, m0, 1));
    m0 = fmaxf(m0, __shfl_xor_sync(0xffffffffu, m0, 2));
    m1 = fmaxf(m1, __shfl_xor_sync(0xffffffffu, m1, 1));
    m1 = fmaxf(m1, __shfl_xor_sync(0xffffffffu, m1, 2));

    float r0 = 0.f, r1 = 0.f;
#pragma unroll
    for (int t = 0; t < 18; t++) {
        s[t][0] = __expf(s[t][0] - m0);
        s[t][1] = __expf(s[t][1] - m0);
        s[t][2] = __expf(s[t][2] - m1);
        s[t][3] = __expf(s[t][3] - m1);
        r0 += s[t][0] + s[t][1];
        r1 += s[t][2] + s[t][3];
    }
    r0 += __shfl_xor_sync(0xffffffffu, r0, 1);
    r0 += __shfl_xor_sync(0xffffffffu, r0, 2);
    r1 += __shfl_xor_sync(0xffffffffu, r1, 1);
    r1 += __shfl_xor_sync(0xffffffffu, r1, 2);
    float inv0 = 1.f / r0, inv1 = 1.f / r1;

    uint32_t ph01[18], ph23[18], pl01[18], pl23[18];
#pragma unroll
    for (int t = 0; t < 18; t++) {
        float p0 = s[t][0] * inv0, p1 = s[t][1] * inv0;
        float p2 = s[t][2] * inv1, p3 = s[t][3] * inv1;
        __nv_bfloat162 h2;
        h2.x = __float2bfloat16(p0); h2.y = __float2bfloat16(p1);
        ph01[t] = *(uint32_t*)&h2;
        pl01[t] = pack_bf2(p0 - __bfloat162float(h2.x), p1 - __bfloat162float(h2.y));
        h2.x = __float2bfloat16(p2); h2.y = __float2bfloat16(p3);
        ph23[t] = *(uint32_t*)&h2;
        pl23[t] = pack_bf2(p2 - __bfloat162float(h2.x), p3 - __bfloat162float(h2.y));
    }

    CP_WAIT(0);
    __syncthreads();

    float o[8][4];
#pragma unroll
    for (int nt = 0; nt < 8; nt++)
#pragma unroll
        for (int e = 0; e < 4; e++) o[nt][e] = 0.f;

    const int vrow_l = ((lane >> 3) & 1) * 8 + (lane & 7);
#pragma unroll
    for (int jl = 0; jl < 9; jl++) {
        uint32_t ah[4] = { ph01[2 * jl], ph23[2 * jl], ph01[2 * jl + 1], ph23[2 * jl + 1] };
        uint32_t al[4] = { pl01[2 * jl], pl23[2 * jl], pl01[2 * jl + 1], pl23[2 * jl + 1] };
        int keyb = (w + jl) * 16;
        uint32_t va_base = sb + A_VH + (uint32_t)(keyb + vrow_l) * APITCHB;
#pragma unroll
        for (int nt = 0; nt < 8; nt++) {
            uint32_t vfh[2], vfl[2];
            uint32_t va = va_base + (uint32_t)nt * 16;
            ldsm_x2t(vfh, va);
            ldsm_x2t(vfl, va + (A_VL - A_VH));
            mma_bf16(o[nt], ah, vfh);
            mma_bf16(o[nt], ah, vfl);
            mma_bf16(o[nt], al, vfh);
        }
    }

    size_t row0 = tok0 + qg0;
    size_t row1 = tok0 + qg1;
#pragma unroll
    for (int nt = 0; nt < 8; nt++) {
        int col = coff + nt * 8 + c2;
        __nv_bfloat162 h2, l2;
        h2.x = __float2bfloat16(o[nt][0]); l2.x = __float2bfloat16(o[nt][0] - __bfloat162float(h2.x));
        h2.y = __float2bfloat16(o[nt][1]); l2.y = __float2bfloat16(o[nt][1] - __bfloat162float(h2.y));
        *(__nv_bfloat162*)(g_ah + row0 * DMODEL + col) = h2;
        *(__nv_bfloat162*)(g_al + row0 * DMODEL + col) = l2;
        h2.x = __float2bfloat16(o[nt][2]); l2.x = __float2bfloat16(o[nt][2] - __bfloat162float(h2.x));
        h2.y = __float2bfloat16(o[nt][3]); l2.y = __float2bfloat16(o[nt][3] - __bfloat162float(h2.y));
        *(__nv_bfloat162*)(g_ah + row1 * DMODEL + col) = h2;
        *(__nv_bfloat162*)(g_al + row1 * DMODEL + col) = l2;
    }
}

// ============================================================
extern "C" void kernel_launch(void* const* d_in, const int* in_sizes, int n_in,
                              void* d_out, int out_size)
{
    const float* x  = (const float*)d_in[0];
    const float* Wq = (const float*)d_in[1];
    const float* bq = (const float*)d_in[2];
    const float* Wk = (const float*)d_in[3];
    const float* bk = (const float*)d_in[4];
    const float* Wv = (const float*)d_in[5];
    const float* bv = (const float*)d_in[6];
    const float* Wo = (const float*)d_in[7];
    const float* bo = (const float*)d_in[8];
    float* out = (float*)d_out;

    cudaFuncSetAttribute(hmma_gemm_kernel, cudaFuncAttributeMaxDynamicSharedMemorySize, GEMM_SMEM);
    cudaFuncSetAttribute(attn_mma_kernel, cudaFuncAttributeMaxDynamicSharedMemorySize, ATTN_SMEM);

    convert_x_kernel<<<MTOT, 256>>>(x);
    convert_w_kernel<<<dim3(DMODEL, 4), 256>>>(Wq, Wk, Wv, Wo);

    dim3 gq(DMODEL / 128, MTOT / 128, 3);
    hmma_gemm_kernel<<<gq, 256, GEMM_SMEM>>>(0, bq, bk, bv, nullptr);

    dim3 ga(SEQ / 64, NHEADS, BATCH);
    attn_mma_kernel<<<ga, 128, ATTN_SMEM>>>();

    dim3 go(DMODEL / 128, MTOT / 128, 1);
    hmma_gemm_kernel<<<go, 256, GEMM_SMEM>>>(1, bo, nullptr, nullptr, out);
}